// round 13
// baseline (speedup 1.0000x reference)
#include <cuda_runtime.h>
#include <cstdint>

// LambdaLoss: B=4096 lists, L=128 items.
// loss = mean over valid lists of
//        [ sum_{i,j: rel_i>rel_j} (rel_i-rel_j)*softplus(-(p_i-p_j)) / cnt ]
//
// softplus(-(p_w-p_l)) = ln(1 + e^{p_l}*e^{-p_w}); precompute e_i, rec_i.
// Counting-sort by rel (ascending): winner = higher sorted index -> pair
// orientation is static per pair form (no data-dependent select).
//
// R13 = R10 engine (4x4 tile, two warps per list, k-parity split; best
// measured: 18.46us) + __launch_bounds__(128,14): caps regs at 36 so 14
// blocks/SM are resident vs 13.84 supplied -> exactly one wave, no ~2us
// second-wave tail.

#define LL_B   4096
#define LL_L   128
#define LOG2E  1.4426950408889634f
#define LN2    0.6931471805599453f

__device__ float g_sum   = 0.0f;
__device__ int   g_valid = 0;
__device__ int   g_done  = 0;

__device__ __forceinline__ float fast_ex2(float x) {
    float r; asm("ex2.approx.f32 %0, %1;" : "=f"(r) : "f"(x)); return r;
}
__device__ __forceinline__ float fast_lg2(float x) {
    float r; asm("lg2.approx.f32 %0, %1;" : "=f"(r) : "f"(x)); return r;
}

__global__ __launch_bounds__(128, 14) void ll_main_kernel(
    const float* __restrict__ pred,
    const float* __restrict__ rel,
    float* __restrict__ out)
{
    // 2 lists per block, 2 warps each. S: sorted (e, rec, rel, _), +16 dup.
    __shared__ float4 S[2][144];
    __shared__ int    hist[2][8];
    __shared__ int    base[2][8];
    __shared__ float  wsum[4];

    const int t    = threadIdx.x;
    const int half = t >> 6;              // which list in this block
    const int t64  = t & 63;              // thread within the list's 2 warps
    const int wl   = (t >> 5) & 1;        // warp-in-list: 0 or 1
    const int lj   = t & 31;
    const int list = blockIdx.x * 2 + half;

    const float* P = pred + list * LL_L;
    const float* R = rel  + list * LL_L;

    // prologue: 64 threads per list handle 2 items each
    const float p0 = P[t64],       r0 = R[t64];
    const float p1 = P[t64 + 64],  r1 = R[t64 + 64];
    const int   c0 = (int)r0, c1 = (int)r1;     // rel in {0..4}
    const float q0 = p0 * LOG2E,  q1 = p1 * LOG2E;
    const float e0 = fast_ex2(q0), rc0 = fast_ex2(-q0);
    const float e1 = fast_ex2(q1), rc1 = fast_ex2(-q1);

    if (t64 < 8) hist[half][t64] = 0;
    __syncthreads();
    atomicAdd(&hist[half][c0], 1);
    atomicAdd(&hist[half][c1], 1);
    __syncthreads();
    if (t64 == 0) {
        int a = 0;
#pragma unroll
        for (int c = 0; c < 5; c++) { base[half][c] = a; a += hist[half][c]; }
    }
    __syncthreads();
    {
        const int pos0 = atomicAdd(&base[half][c0], 1);
        const int pos1 = atomicAdd(&base[half][c1], 1);
        const float4 u0 = make_float4(e0, rc0, r0, 0.0f);
        const float4 u1 = make_float4(e1, rc1, r1, 0.0f);
        S[half][pos0] = u0;
        S[half][pos1] = u1;
        if (pos0 < 16) S[half][pos0 + 128] = u0;
        if (pos1 < 16) S[half][pos1 + 128] = u1;
    }
    __syncthreads();

    const float4* Sw = S[half];
    const float4 sa = Sw[lj];
    const float4 sb = Sw[lj + 32];
    const float4 sc = Sw[lj + 64];
    const float4 sd = Sw[lj + 96];
    const float eA = sa.x, cA = sa.y, rA = sa.z;
    const float eB = sb.x, cB = sb.y, rB = sb.z;
    const float eC = sc.x, cC = sc.y, rC = sc.z;
    const float eD = sd.x, cD = sd.y, rD = sd.z;

    float acc0 = 0.0f, acc1 = 0.0f, acc2 = 0.0f, acc3 = 0.0f;

    // partner (higher sorted index) wins: t = e_self*rec_p, rd = r_p - r_s >= 0
#define PW(V, ES, RS, ACC) \
    ACC = fmaf((V).z - (RS), fast_lg2(fmaf((ES), (V).y, 1.0f)), ACC);
    // self (higher sorted index) wins: t = e_p*rec_self, rd = r_s - r_p >= 0
#define SW(V, CS, RS, ACC) \
    ACC = fmaf((RS) - (V).z, fast_lg2(fmaf((V).x, (CS), 1.0f)), ACC);
    // dynamic (v4 may wrap): wrapped -> self wins, else partner wins
#define DYN(V, WR, ES, CS, RS, ACC)                                       \
    {                                                                     \
        float tt = (WR) ? fmaf((V).x, (CS), 1.0f)                         \
                        : fmaf((ES), (V).y, 1.0f);                        \
        ACC = fmaf(fabsf((V).z - (RS)), fast_lg2(tt), ACC);               \
    }

    // warp0: k = 1,3,...,15   warp1: k = 2,4,...,14 (k=16 tail below)
#pragma unroll
    for (int kk = 0; kk < 7; kk++) {
        const int k = 1 + wl + 2 * kk;
        const float4 v1 = Sw[lj + k];
        const float4 v2 = Sw[lj + 32 + k];
        const float4 v3 = Sw[lj + 64 + k];
        const float4 v4 = Sw[lj + 96 + k];
        const bool  wr = (lj + 96 + k) >= LL_L;

        // d = k
        PW(v1, eA, rA, acc0)  PW(v2, eB, rB, acc1)  PW(v3, eC, rC, acc2)
        DYN(v4, wr, eD, cD, rD, acc3)
        // d = 32+k
        PW(v2, eA, rA, acc0)  PW(v3, eB, rB, acc1)
        DYN(v4, wr, eC, cC, rC, acc2)
        SW(v1, cD, rD, acc3)
        // d = 64-k
        PW(v3, eA, rA, acc0)
        DYN(v4, wr, eB, cB, rB, acc1)
        SW(v1, cC, rC, acc2)  SW(v2, cD, rD, acc3)
        // d = 32-k
        DYN(v4, wr, eA, cA, rA, acc0)
        SW(v1, cB, rB, acc1)  SW(v2, cC, rC, acc2)  SW(v3, cD, rD, acc3)
    }

    if (wl == 0) {
        // k = 15 (last odd)
        const int k = 15;
        const float4 v1 = Sw[lj + k];
        const float4 v2 = Sw[lj + 32 + k];
        const float4 v3 = Sw[lj + 64 + k];
        const float4 v4 = Sw[lj + 96 + k];
        const bool  wr = (lj + 96 + k) >= LL_L;
        PW(v1, eA, rA, acc0)  PW(v2, eB, rB, acc1)  PW(v3, eC, rC, acc2)
        DYN(v4, wr, eD, cD, rD, acc3)
        PW(v2, eA, rA, acc0)  PW(v3, eB, rB, acc1)
        DYN(v4, wr, eC, cC, rC, acc2)
        SW(v1, cD, rD, acc3)
        PW(v3, eA, rA, acc0)
        DYN(v4, wr, eB, cB, rB, acc1)
        SW(v1, cC, rC, acc2)  SW(v2, cD, rD, acc3)
        DYN(v4, wr, eA, cA, rA, acc0)
        SW(v1, cB, rB, acc1)  SW(v2, cC, rC, acc2)  SW(v3, cD, rD, acc3)

        // register-only pairs: d=32 (A-B,B-C,C-D,D-A) and d=64 (A-C,B-D)
        acc0 = fmaf(rB - rA, fast_lg2(fmaf(eA, cB, 1.0f)), acc0);
        acc1 = fmaf(rC - rB, fast_lg2(fmaf(eB, cC, 1.0f)), acc1);
        acc2 = fmaf(rD - rC, fast_lg2(fmaf(eC, cD, 1.0f)), acc2);
        acc3 = fmaf(rD - rA, fast_lg2(fmaf(eA, cD, 1.0f)), acc3);
        acc0 = fmaf(rC - rA, fast_lg2(fmaf(eA, cC, 1.0f)), acc0);
        acc1 = fmaf(rD - rB, fast_lg2(fmaf(eB, cD, 1.0f)), acc1);
    } else {
        // k = 16: d=16 and d=48 only (other forms would duplicate)
        const float4 v1 = Sw[lj + 16];
        const float4 v2 = Sw[lj + 48];
        const float4 v3 = Sw[lj + 80];
        const float4 v4 = Sw[lj + 112];
        const bool  wr = (lj + 112) >= LL_L;
        PW(v1, eA, rA, acc0)  PW(v2, eB, rB, acc1)  PW(v3, eC, rC, acc2)
        DYN(v4, wr, eD, cD, rD, acc3)
        PW(v2, eA, rA, acc0)  PW(v3, eB, rB, acc1)
        DYN(v4, wr, eC, cC, rC, acc2)
        SW(v1, cD, rD, acc3)
    }

#undef PW
#undef SW
#undef DYN

    float acc = (acc0 + acc1) + (acc2 + acc3);

    // warp reduction, then combine the list's two warps
#pragma unroll
    for (int off = 16; off; off >>= 1)
        acc += __shfl_xor_sync(0xffffffffu, acc, off);
    if (lj == 0) wsum[t >> 5] = acc;
    __syncthreads();

    if (t64 == 0) {
        float s = (wsum[half * 2] + wsum[half * 2 + 1]) * LN2;
        const int n0 = hist[half][0], n1 = hist[half][1], n2 = hist[half][2];
        const int n3 = hist[half][3], n4 = hist[half][4];
        const int cnt = n1 * n0
                      + n2 * (n0 + n1)
                      + n3 * (n0 + n1 + n2)
                      + n4 * (n0 + n1 + n2 + n3);
        if (cnt > 0) {
            atomicAdd(&g_sum, s / (float)cnt);
            atomicAdd(&g_valid, 1);
        }
        __threadfence();
        const int prev = atomicAdd(&g_done, 1);
        if (prev == LL_B - 1) {
            const float gs = g_sum;
            const int   gv = g_valid;
            out[0] = (gv > 0) ? (gs / (float)gv) : 0.0f;
            g_sum   = 0.0f;
            g_valid = 0;
            g_done  = 0;
        }
    }
}

extern "C" void kernel_launch(void* const* d_in, const int* in_sizes, int n_in,
                              void* d_out, int out_size)
{
    const float* pred = (const float*)d_in[0];
    const float* rel  = (const float*)d_in[1];
    float* out = (float*)d_out;

    ll_main_kernel<<<LL_B / 2, 128>>>(pred, rel, out);
}

// round 14
// speedup vs baseline: 1.2262x; 1.2262x over previous
#include <cuda_runtime.h>
#include <cstdint>

// LambdaLoss: B=4096 lists, L=128 items.
// loss = mean over valid lists of
//        [ sum_{i,j: rel_i>rel_j} (rel_i-rel_j)*softplus(-(p_i-p_j)) / cnt ]
//
// R14 — class-segment product accumulation (0 MUFU per pair):
// softplus(-(p_w-p_l)) = ln(1 + e_l*rec_w) with e=exp(p), rec=exp(-p).
// Counting-sort by rel. For loser item i (class myc) and winner class
// cb > myc, ALL pairs share weight (cb-myc), and the winners are the
// CONTIGUOUS sorted range [cumB[cb], cumB[cb+1]). So:
//   contrib_i = sum_{cb>myc} (cb-myc) * log2( prod_j (1 + e_i*rec_j) )
// Inner loop per pair: 1 broadcast LDS.32 + FFMA + FMUL. Exponent
// harvesting every 4 multiplies keeps the product in range; ONE lg2 per
// segment (<=4 per thread) instead of one per pair (127). Same-class
// pairs (weight 0) are never enumerated.

#define LL_B   4096
#define LL_L   128
#define LOG2E  1.4426950408889634f
#define LN2    0.6931471805599453f

__device__ float g_sum   = 0.0f;
__device__ int   g_valid = 0;
__device__ int   g_done  = 0;

__device__ __forceinline__ float fast_ex2(float x) {
    float r; asm("ex2.approx.f32 %0, %1;" : "=f"(r) : "f"(x)); return r;
}
__device__ __forceinline__ float fast_lg2(float x) {
    float r; asm("lg2.approx.f32 %0, %1;" : "=f"(r) : "f"(x)); return r;
}

__global__ __launch_bounds__(128) void ll_main_kernel(
    const float* __restrict__ pred,
    const float* __restrict__ rel,
    float* __restrict__ out)
{
    __shared__ float Se[LL_L];     // e by sorted index
    __shared__ float Srec[LL_L];   // rec by sorted index
    __shared__ int   hist[8];
    __shared__ int   base[8];
    __shared__ int   cumB[6];      // class boundaries in sorted order
    __shared__ float wsum[4];

    const int t    = threadIdx.x;
    const int list = blockIdx.x;

    const float p = pred[list * LL_L + t];
    const float r = rel [list * LL_L + t];
    const int   c = (int)r;                 // rel in {0..4}
    const float q = p * LOG2E;
    const float e  = fast_ex2(q);
    const float rc = fast_ex2(-q);

    if (t < 8) hist[t] = 0;
    __syncthreads();
    atomicAdd(&hist[c], 1);
    __syncthreads();
    if (t == 0) {
        int a = 0;
#pragma unroll
        for (int cc = 0; cc < 5; cc++) { cumB[cc] = a; base[cc] = a; a += hist[cc]; }
        cumB[5] = a;   // == 128
    }
    __syncthreads();
    {
        const int pos = atomicAdd(&base[c], 1);
        Se[pos]   = e;
        Srec[pos] = rc;
    }
    __syncthreads();

    // thread t owns SORTED item t (the loser side of its pairs)
    const float eS = Se[t];
    const int b1 = cumB[1], b2 = cumB[2], b3 = cumB[3], b4 = cumB[4];
    const int myc = (t >= b1) + (t >= b2) + (t >= b3) + (t >= b4);

    float acc = 0.0f;   // sum of w * log2-units

#pragma unroll
    for (int cb = 1; cb <= 4; cb++) {
        const int w = cb - myc;
        // skip if no lane in this warp pairs into class cb
        if (__all_sync(0xffffffffu, w <= 0)) continue;

        const int j0 = cumB[cb];
        const int j1 = cumB[cb + 1];

        float prod = 1.0f;
        int   expo = 0;
        int   j    = j0;
        for (; j + 4 <= j1; j += 4) {
            // all lanes read the same j -> broadcast, conflict-free
            const float x0 = fmaf(eS, Srec[j    ], 1.0f);
            const float x1 = fmaf(eS, Srec[j + 1], 1.0f);
            const float x2 = fmaf(eS, Srec[j + 2], 1.0f);
            const float x3 = fmaf(eS, Srec[j + 3], 1.0f);
            prod *= (x0 * x1) * (x2 * x3);        // < 2^68, no overflow
            // harvest exponent, renormalize mantissa to [1,2)
            const unsigned u = __float_as_uint(prod);
            expo += (int)(u >> 23) - 127;
            prod  = __uint_as_float((u & 0x007fffffu) | 0x3f800000u);
        }
        for (; j < j1; j++)                        // <=3 remainder pairs
            prod *= fmaf(eS, Srec[j], 1.0f);
        {
            const unsigned u = __float_as_uint(prod);
            expo += (int)(u >> 23) - 127;
            prod  = __uint_as_float((u & 0x007fffffu) | 0x3f800000u);
        }

        const float seg = (float)expo + fast_lg2(prod);
        if (w > 0) acc = fmaf((float)w, seg, acc);
    }

    // block reduction (4 warps)
#pragma unroll
    for (int off = 16; off; off >>= 1)
        acc += __shfl_xor_sync(0xffffffffu, acc, off);
    if ((t & 31) == 0) wsum[t >> 5] = acc;
    __syncthreads();

    if (t == 0) {
        const float s = (wsum[0] + wsum[1] + wsum[2] + wsum[3]) * LN2;
        const int n0 = hist[0], n1 = hist[1], n2 = hist[2];
        const int n3 = hist[3], n4 = hist[4];
        const int cnt = n1 * n0
                      + n2 * (n0 + n1)
                      + n3 * (n0 + n1 + n2)
                      + n4 * (n0 + n1 + n2 + n3);
        if (cnt > 0) {
            atomicAdd(&g_sum, s / (float)cnt);
            atomicAdd(&g_valid, 1);
        }
        __threadfence();
        const int prev = atomicAdd(&g_done, 1);
        if (prev == gridDim.x - 1) {
            const float gs = g_sum;
            const int   gv = g_valid;
            out[0] = (gv > 0) ? (gs / (float)gv) : 0.0f;
            g_sum   = 0.0f;
            g_valid = 0;
            g_done  = 0;
        }
    }
}

extern "C" void kernel_launch(void* const* d_in, const int* in_sizes, int n_in,
                              void* d_out, int out_size)
{
    const float* pred = (const float*)d_in[0];
    const float* rel  = (const float*)d_in[1];
    float* out = (float*)d_out;

    ll_main_kernel<<<LL_B, LL_L>>>(pred, rel, out);
}

// round 15
// speedup vs baseline: 1.2448x; 1.0152x over previous
#include <cuda_runtime.h>
#include <cstdint>

// LambdaLoss: B=4096 lists, L=128 items.
// loss = mean over valid lists of
//        [ sum_{i,j: rel_i>rel_j} (rel_i-rel_j)*softplus(-(p_i-p_j)) / cnt ]
//
// R15 — telescoped prefix-product formulation (0 MUFU per pair, no weights):
// softplus(-(p_w-p_l)) = ln(1 + e_l*rec_w). Counting-sort by rel. For winner
// item j (sorted index t, class ct) the weighted sum over its losers
// telescopes:  sum_{i:ci<ct} (ct-ci)*log2(x_i) = sum_{m=1..ct} P_m,
// where P_m = log2 PROD_{i < cumB[m]} x_i  (prefix product over losers of
// class < m). So each thread keeps ONE running product over ascending sorted
// losers and just ADDS the current log at each class boundary m <= ct.
// Inner loop: float4 loads (4 partners per LDS.128), dual product chains
// (p0/p1) harvested via exponent extraction -> FFMA+FMUL per pair, ~2.4
// issue slots/pair, lg2 only at <=4 checkpoints per thread.

#define LL_B   4096
#define LL_L   128
#define LOG2E  1.4426950408889634f
#define LN2    0.6931471805599453f

__device__ float g_sum   = 0.0f;
__device__ int   g_valid = 0;
__device__ int   g_done  = 0;

__device__ __forceinline__ float fast_ex2(float x) {
    float r; asm("ex2.approx.f32 %0, %1;" : "=f"(r) : "f"(x)); return r;
}
__device__ __forceinline__ float fast_lg2(float x) {
    float r; asm("lg2.approx.f32 %0, %1;" : "=f"(r) : "f"(x)); return r;
}

// extract exponent into expo, renormalize mantissa to [1,2)
#define HARVEST(P)                                                        \
    {                                                                     \
        const unsigned _u = __float_as_uint(P);                           \
        expo += (int)(_u >> 23) - 127;                                    \
        (P) = __uint_as_float((_u & 0x007fffffu) | 0x3f800000u);          \
    }

__global__ __launch_bounds__(128) void ll_main_kernel(
    const float* __restrict__ pred,
    const float* __restrict__ rel,
    float* __restrict__ out)
{
    __shared__ float Se[LL_L];     // e  by sorted index (losers, read as float4)
    __shared__ float Srec[LL_L];   // rec by sorted index (self factor)
    __shared__ int   hist[8];
    __shared__ int   base[8];
    __shared__ int   cumB[6];
    __shared__ float wsum[4];

    const int t    = threadIdx.x;
    const int list = blockIdx.x;

    const float p = pred[list * LL_L + t];
    const float r = rel [list * LL_L + t];
    const int   c = (int)r;                 // rel in {0..4}
    const float q = p * LOG2E;
    const float e  = fast_ex2(q);
    const float rc = fast_ex2(-q);

    if (t < 8) hist[t] = 0;
    __syncthreads();
    atomicAdd(&hist[c], 1);
    __syncthreads();
    if (t == 0) {
        int a = 0;
#pragma unroll
        for (int cc = 0; cc < 5; cc++) { cumB[cc] = a; base[cc] = a; a += hist[cc]; }
        cumB[5] = a;   // == 128
    }
    __syncthreads();
    {
        const int pos = atomicAdd(&base[c], 1);
        Se[pos]   = e;
        Srec[pos] = rc;
    }
    __syncthreads();

    // thread t = WINNER side of its pairs (sorted item t)
    const float recS = Srec[t];
    const int b1 = cumB[1], b2 = cumB[2], b3 = cumB[3], b4 = cumB[4];
    const int ct = (t >= b1) + (t >= b2) + (t >= b3) + (t >= b4);

    float acc = 0.0f;
    float p0 = 1.0f, p1 = 1.0f;
    int   expo = 0;
    int   j = 0;

#pragma unroll
    for (int m = 1; m <= 4; m++) {
        // if no lane in this warp wins against class (m-1) or above, done
        if (__all_sync(0xffffffffu, ct < m)) break;

        const int j1 = cumB[m];

        // scalar head to 16B alignment (block-uniform trip count)
        while (j < j1 && (j & 3)) { p0 *= fmaf(recS, Se[j], 1.0f); j++; }
        // bulk: 8 losers per iteration, dual chains, one harvest each
        while (j + 8 <= j1) {
            const float4 va = *reinterpret_cast<const float4*>(&Se[j]);
            const float4 vb = *reinterpret_cast<const float4*>(&Se[j + 4]);
            const float g0 = (fmaf(recS, va.x, 1.0f) * fmaf(recS, va.y, 1.0f))
                           * (fmaf(recS, va.z, 1.0f) * fmaf(recS, va.w, 1.0f));
            const float g1 = (fmaf(recS, vb.x, 1.0f) * fmaf(recS, vb.y, 1.0f))
                           * (fmaf(recS, vb.z, 1.0f) * fmaf(recS, vb.w, 1.0f));
            p0 *= g0;  HARVEST(p0)
            p1 *= g1;  HARVEST(p1)
            j += 8;
        }
        if (j + 4 <= j1) {
            const float4 va = *reinterpret_cast<const float4*>(&Se[j]);
            const float g0 = (fmaf(recS, va.x, 1.0f) * fmaf(recS, va.y, 1.0f))
                           * (fmaf(recS, va.z, 1.0f) * fmaf(recS, va.w, 1.0f));
            p0 *= g0;  HARVEST(p0)
            j += 4;
        }
        while (j < j1) { p0 *= fmaf(recS, Se[j], 1.0f); j++; }

        // checkpoint: current prefix log = expo + lg2(p0*p1)
        HARVEST(p0)
        HARVEST(p1)
        const float curlog = (float)expo + fast_lg2(p0 * p1);  // p0*p1 < 4
        if (ct >= m) acc += curlog;
    }

    // block reduction (4 warps)
#pragma unroll
    for (int off = 16; off; off >>= 1)
        acc += __shfl_xor_sync(0xffffffffu, acc, off);
    if ((t & 31) == 0) wsum[t >> 5] = acc;
    __syncthreads();

    if (t == 0) {
        const float s = (wsum[0] + wsum[1] + wsum[2] + wsum[3]) * LN2;
        const int n0 = hist[0], n1 = hist[1], n2 = hist[2];
        const int n3 = hist[3], n4 = hist[4];
        const int cnt = n1 * n0
                      + n2 * (n0 + n1)
                      + n3 * (n0 + n1 + n2)
                      + n4 * (n0 + n1 + n2 + n3);
        if (cnt > 0) {
            atomicAdd(&g_sum, s / (float)cnt);
            atomicAdd(&g_valid, 1);
        }
        __threadfence();
        const int prev = atomicAdd(&g_done, 1);
        if (prev == gridDim.x - 1) {
            const float gs = g_sum;
            const int   gv = g_valid;
            out[0] = (gv > 0) ? (gs / (float)gv) : 0.0f;
            g_sum   = 0.0f;
            g_valid = 0;
            g_done  = 0;
        }
    }
}

extern "C" void kernel_launch(void* const* d_in, const int* in_sizes, int n_in,
                              void* d_out, int out_size)
{
    const float* pred = (const float*)d_in[0];
    const float* rel  = (const float*)d_in[1];
    float* out = (float*)d_out;

    ll_main_kernel<<<LL_B, LL_L>>>(pred, rel, out);
}